// round 14
// baseline (speedup 1.0000x reference)
#include <cuda_runtime.h>
#include <cuda_bf16.h>
#include <math.h>
#include <stdint.h>

// Problem constants
#define BSZ   4
#define LSEQ  2048
#define DMOD  1024
#define NHEAD 16
#define HDIM  64
#define MROWS (BSZ * LSEQ)      // 8192
#define NQKV  (3 * DMOD)        // 3072

// Scratch (allocation-free rule: device globals)
__device__ __align__(16) float g_qkv[(size_t)MROWS * NQKV];   // [B*L, 3D] row-major
__device__ __align__(16) float g_y[(size_t)MROWS * DMOD];     // attn out, FRAG-A layout
__device__ __align__(16) float g_xr[(size_t)MROWS * DMOD];    // x rounded, FRAG-A layout
__device__ __align__(16) float g_wqkvr[(size_t)DMOD * NQKV];  // Wqkv rounded, FRAG-B
__device__ __align__(16) float g_wprojr[(size_t)DMOD * DMOD]; // Wproj rounded, FRAG-B
// Pre-converted KV: per (bh, jtile): [Khi 2048w][Klo 2048w], frag-unit tiles
__device__ __align__(16) uint32_t g_kw[(size_t)64 * 32 * 2 * 2048];
__device__ __align__(16) uint32_t g_vw[(size_t)64 * 32 * 2 * 2048];

// ===========================================================================
// Helpers
// ===========================================================================
__device__ __forceinline__ uint32_t smem_u32(const void* p) {
    uint32_t a;
    asm("{ .reg .u64 t; cvta.to.shared.u64 t, %1; cvt.u32.u64 %0, t; }"
        : "=r"(a) : "l"(p));
    return a;
}
__device__ __forceinline__ void cp_async16(uint32_t dst, const void* src) {
    asm volatile("cp.async.cg.shared.global [%0], [%1], 16;"
                 :: "r"(dst), "l"(src) : "memory");
}
__device__ __forceinline__ void cp_commit() {
    asm volatile("cp.async.commit_group;" ::: "memory");
}
#define CP_WAIT(n) asm volatile("cp.async.wait_group %0;" :: "n"(n) : "memory")

__device__ __forceinline__ uint32_t f2tf32(float f) {
    uint32_t r;
    asm("cvt.rna.tf32.f32 %0, %1;" : "=r"(r) : "f"(f));
    return r;
}
__device__ __forceinline__ void mma_tf32(float* c, const uint32_t* a, const uint32_t* b) {
    asm volatile(
        "mma.sync.aligned.m16n8k8.row.col.f32.tf32.tf32.f32 "
        "{%0,%1,%2,%3}, {%4,%5,%6,%7}, {%8,%9}, {%0,%1,%2,%3};\n"
        : "+f"(c[0]), "+f"(c[1]), "+f"(c[2]), "+f"(c[3])
        : "r"(a[0]), "r"(a[1]), "r"(a[2]), "r"(a[3]), "r"(b[0]), "r"(b[1]));
}
__device__ __forceinline__ uint32_t pk_bf16(float x, float y) {
    uint32_t r;
    asm("cvt.rn.bf16x2.f32 %0, %1, %2;" : "=r"(r) : "f"(y), "f"(x));
    return r;
}
__device__ __forceinline__ float bflo(uint32_t u) { return __uint_as_float(u << 16); }
__device__ __forceinline__ float bfhi(uint32_t u) { return __uint_as_float(u & 0xffff0000u); }

__device__ __forceinline__ void mma_bf16(float* c, const uint32_t* a,
                                         uint32_t b0, uint32_t b1) {
    asm volatile(
        "mma.sync.aligned.m16n8k16.row.col.f32.bf16.bf16.f32 "
        "{%0,%1,%2,%3}, {%4,%5,%6,%7}, {%8,%9}, {%0,%1,%2,%3};\n"
        : "+f"(c[0]), "+f"(c[1]), "+f"(c[2]), "+f"(c[3])
        : "r"(a[0]), "r"(a[1]), "r"(a[2]), "r"(a[3]), "r"(b0), "r"(b1));
}

// K/V tile word address: logical word c (2 elems each), row; unit XOR-rotated.
__device__ __forceinline__ int kaddr(int c, int row) {
    int kc = c >> 3, t = (c >> 2) & 1, q = c & 3;
    int u = q * 2 + (kc >> 1);
    int w = (kc & 1) * 2 + t;
    return row * 32 + ((u ^ (row & 7)) << 2) + w;
}

// ===========================================================================
// Fragment-major GEMM operand layouts (unchanged from round 12)
// ===========================================================================
__global__ void xfrag_kernel(const float* __restrict__ in, float* __restrict__ out,
                             int M, int K)
{
    int id = blockIdx.x * blockDim.x + threadIdx.x;
    if (id < M * K) {
        int m = id / K, k = id % K;
        float v = __uint_as_float(f2tf32(in[id]));
        int blk = (m >> 4) * (K >> 3) + (k >> 3);
        int inner = ((m & 7) * 4 + (k & 3)) * 4 + ((k >> 2) & 1) * 2 + ((m >> 3) & 1);
        out[(size_t)blk * 128 + inner] = v;
    }
}
__global__ void wfrag_kernel(const float* __restrict__ in, float* __restrict__ out,
                             int K, int N)
{
    int id = blockIdx.x * blockDim.x + threadIdx.x;
    if (id < K * N) {
        int k = id / N, n = id % N;
        float v = __uint_as_float(f2tf32(in[id]));
        int blk = (n >> 3) * (K >> 3) + (k >> 3);
        int inner = ((n & 7) * 4 + (k & 3)) * 2 + ((k >> 2) & 1);
        out[(size_t)blk * 64 + inner] = v;
    }
}

// ===========================================================================
// Pre-pass: K/V fp32 -> frag-unit bf16 hi/lo gmem tiles (unchanged)
// ===========================================================================
__global__ __launch_bounds__(128)
void kvconv_kernel(const float* __restrict__ qkv,
                   uint32_t* __restrict__ kw, uint32_t* __restrict__ vw)
{
    const int tid = threadIdx.x;
    const int jt  = blockIdx.x;
    const int bh  = blockIdx.y;
    const int b   = bh >> 4;
    const int h   = bh & 15;
    const int k0  = jt * 64;
    const float* base = qkv + (size_t)(b * LSEQ) * NQKV + h * HDIM;

    uint32_t* kh = kw + ((size_t)(bh * 32 + jt) * 2) * 2048;
    uint32_t* kl = kh + 2048;
    uint32_t* vh = vw + ((size_t)(bh * 32 + jt) * 2) * 2048;
    uint32_t* vl = vh + 2048;

    {
        const int j    = tid & 63;
        const int half = tid >> 6;
        const float* src = base + DMOD + (size_t)(k0 + j) * NQKV + half * 32;
        #pragma unroll
        for (int i = 0; i < 8; i++) {
            float4 k4 = *(const float4*)&src[4 * i];
            uint32_t h0 = pk_bf16(k4.x, k4.y);
            uint32_t h1 = pk_bf16(k4.z, k4.w);
            int c = half * 16 + 2 * i;
            kh[kaddr(c, j)]     = h0;
            kh[kaddr(c + 1, j)] = h1;
            kl[kaddr(c, j)]     = pk_bf16(k4.x - bflo(h0), k4.y - bfhi(h0));
            kl[kaddr(c + 1, j)] = pk_bf16(k4.z - bflo(h1), k4.w - bfhi(h1));
        }
    }
    {
        const int jp = tid & 31;
        const int d0 = (tid >> 5) << 4;
        const float* r0 = base + 2 * DMOD + (size_t)(k0 + 2 * jp) * NQKV + d0;
        const float* r1 = r0 + NQKV;
        #pragma unroll
        for (int i4 = 0; i4 < 4; i4++) {
            float4 x = *(const float4*)&r0[4 * i4];
            float4 yv = *(const float4*)&r1[4 * i4];
            float xs[4] = {x.x, x.y, x.z, x.w};
            float ys[4] = {yv.x, yv.y, yv.z, yv.w};
            #pragma unroll
            for (int e = 0; e < 4; e++) {
                int d = d0 + 4 * i4 + e;
                uint32_t hi = pk_bf16(xs[e], ys[e]);
                vh[kaddr(jp, d)] = hi;
                vl[kaddr(jp, d)] = pk_bf16(xs[e] - bflo(hi), ys[e] - bfhi(hi));
            }
        }
    }
}

// ===========================================================================
// tf32 tensor-core GEMM + bias, FRAG-MAJOR A/B inputs (unchanged round 12)
// ===========================================================================
#define GSTAGES 4
#define GBK 16
#define A_STAGE_B 8192
#define B_STAGE_B 8192
#define ST_B (A_STAGE_B + B_STAGE_B)
#define GEMM_SMEM (GSTAGES * ST_B)    // 65536

__global__ __launch_bounds__(256, 2)
void gemm_tc(const float* __restrict__ A, const float* __restrict__ W,
             const float* __restrict__ bias, float* __restrict__ C,
             int M, int N, int K)
{
    extern __shared__ __align__(16) float sm_f[];
    const uint32_t sm_b = smem_u32(sm_f);

    const int tid  = threadIdx.x;
    const int wid  = tid >> 5;
    const int lane = tid & 31;
    const int grp  = lane >> 2;
    const int qid  = lane & 3;
    const int wm   = wid >> 2;
    const int wn   = wid & 3;
    const int m0   = blockIdx.y * 128;
    const int n0   = blockIdx.x * 128;
    const int NCHUNK = K / GBK;
    const int KB = K >> 3;

    float acc[4][4][4];
    #pragma unroll
    for (int mi = 0; mi < 4; mi++)
        #pragma unroll
        for (int ni = 0; ni < 4; ni++)
            #pragma unroll
            for (int q = 0; q < 4; q++) acc[mi][ni][q] = 0.0f;

    auto load_stage = [&](int s, int kc0) {
        const uint32_t as = sm_b + s * ST_B;
        const uint32_t bs = as + A_STAGE_B;
        const int kb = kc0 >> 3;
        #pragma unroll
        for (int i = 0; i < 2; i++) {
            int id   = tid + i * 256;
            int mblk = id >> 6;
            int off  = id & 63;
            const float* src = A + ((size_t)((m0 >> 4) + mblk) * KB + kb) * 128 + off * 4;
            cp_async16(as + mblk * 1024 + off * 16, src);
        }
        #pragma unroll
        for (int i = 0; i < 2; i++) {
            int id   = tid + i * 256;
            int nblk = id >> 5;
            int off  = id & 31;
            const float* src = W + ((size_t)((n0 >> 3) + nblk) * KB + kb) * 64 + off * 4;
            cp_async16(bs + nblk * 512 + off * 16, src);
        }
        cp_commit();
    };

    #pragma unroll
    for (int s = 0; s < GSTAGES - 1; s++) load_stage(s, s * GBK);

    for (int c = 0; c < NCHUNK; c++) {
        CP_WAIT(GSTAGES - 2);
        __syncthreads();
        {
            int nc = c + GSTAGES - 1;
            if (nc < NCHUNK) load_stage(nc % GSTAGES, nc * GBK);
        }

        const float* as = sm_f + (c % GSTAGES) * (ST_B / 4);
        const float* bs = as + A_STAGE_B / 4;

        #pragma unroll
        for (int ks = 0; ks < 2; ks++) {
            uint32_t af[4][4], bf[4][2];
            #pragma unroll
            for (int mi = 0; mi < 4; mi++) {
                const float4 fa = *(const float4*)
                    &as[((wm * 4 + mi) * 2 + ks) * 128 + lane * 4];
                af[mi][0] = __float_as_uint(fa.x);
                af[mi][1] = __float_as_uint(fa.y);
                af[mi][2] = __float_as_uint(fa.z);
                af[mi][3] = __float_as_uint(fa.w);
            }
            #pragma unroll
            for (int ni = 0; ni < 4; ni++) {
                const float2 fb = *(const float2*)
                    &bs[((wn * 4 + ni) * 2 + ks) * 64 + lane * 2];
                bf[ni][0] = __float_as_uint(fb.x);
                bf[ni][1] = __float_as_uint(fb.y);
            }
            #pragma unroll
            for (int mi = 0; mi < 4; mi++)
                #pragma unroll
                for (int ni = 0; ni < 4; ni++)
                    mma_tf32(acc[mi][ni], af[mi], bf[ni]);
        }
    }

    #pragma unroll
    for (int mi = 0; mi < 4; mi++) {
        int r0 = m0 + wm * 64 + mi * 16 + grp;
        #pragma unroll
        for (int ni = 0; ni < 4; ni++) {
            int col = n0 + wn * 32 + ni * 8 + qid * 2;
            float2 bv = *(const float2*)&bias[col];
            float2 o0, o1;
            o0.x = acc[mi][ni][0] + bv.x;  o0.y = acc[mi][ni][1] + bv.y;
            o1.x = acc[mi][ni][2] + bv.x;  o1.y = acc[mi][ni][3] + bv.y;
            *(float2*)&C[(size_t)r0 * N + col]       = o0;
            *(float2*)&C[(size_t)(r0 + 8) * N + col] = o1;
        }
    }
}

// ===========================================================================
// Flash-attention (causal), bf16 3-term mma.sync; frag-unit K/V tiles.
// Round-14: q-tile 128 (256 threads, 8 warps x 16 rows). Halves K/V L2
// traffic and barrier count per warp-tile; warps/SM 12 -> 16.
// Per-q-row arithmetic is bit-identical to round 13 (masked tiles produce
// exp()=0 and alpha=1).
// ===========================================================================
#define ATT_STAGE_W 8192
#define ATTN_SMEM (2 * ATT_STAGE_W * 4)   // 65536 B

__global__ __launch_bounds__(256, 2)
void attn_mma(const float* __restrict__ qkv,
              const uint32_t* __restrict__ kw, const uint32_t* __restrict__ vw,
              float* __restrict__ y)
{
    extern __shared__ __align__(16) uint32_t sm_w[];
    const uint32_t sm_b = smem_u32(sm_w);

    const int tid  = threadIdx.x;
    const int wid  = tid >> 5;       // 0..7
    const int lane = tid & 31;
    const int grp  = lane >> 2;
    const int qid  = lane & 3;

    const int qt = gridDim.x - 1 - blockIdx.x;   // long rows first
    const int bh = blockIdx.y;
    const int b  = bh >> 4;
    const int h  = bh & 15;
    const int q0 = qt * 128;
    const int ktmax = 2 * qt + 1;    // k-tiles 0..ktmax cover causal span

    const float* base = qkv + (size_t)(b * LSEQ) * NQKV + h * HDIM;
    const char* gk_base = (const char*)(kw + (size_t)bh * 32 * 2 * 2048);
    const char* gv_base = (const char*)(vw + (size_t)bh * 32 * 2 * 2048);

    // ---- Q fragments (hi/lo bf16) ----
    uint32_t qh[4][4], ql[4][4];
    const int i0 = q0 + wid * 16 + grp;
    #pragma unroll
    for (int kc = 0; kc < 4; kc++)
        #pragma unroll
        for (int hh = 0; hh < 2; hh++)
            #pragma unroll
            for (int rr = 0; rr < 2; rr++) {
                const float* p = base + (size_t)(i0 + 8 * rr) * NQKV
                               + kc * 16 + hh * 8 + 2 * qid;
                float2 v = *(const float2*)p;
                uint32_t hi = pk_bf16(v.x, v.y);
                qh[kc][2 * hh + rr] = hi;
                ql[kc][2 * hh + rr] = pk_bf16(v.x - bflo(hi), v.y - bfhi(hi));
            }

    float o[8][4];
    #pragma unroll
    for (int nt = 0; nt < 8; nt++)
        #pragma unroll
        for (int c = 0; c < 4; c++) o[nt][c] = 0.0f;
    float m0f = -1e30f, m1f = -1e30f, l0 = 0.0f, l1 = 0.0f;

    auto prefetch = [&](int kt, int s) {
        const char* gk = gk_base + (size_t)kt * 16384;
        const char* gv = gv_base + (size_t)kt * 16384;
        const uint32_t dst = sm_b + s * (ATT_STAGE_W * 4);
        #pragma unroll
        for (int i = 0; i < 8; i++) {
            int id = tid + i * 256;          // 0..2047
            const char* src = (id < 1024) ? (gk + id * 16)
                                          : (gv + (id - 1024) * 16);
            cp_async16(dst + id * 16, src);
        }
        cp_commit();
    };

    prefetch(0, 0);

    const int u0 = qid * 2;
    const int u1 = qid * 2 + 1;

    for (int kt = 0; kt <= ktmax; kt++) {
        const int k0 = kt * 64;
        const int s  = kt & 1;
        CP_WAIT(0);
        __syncthreads();
        if (kt < ktmax) prefetch(kt + 1, s ^ 1);

        const uint32_t* KhiW = sm_w + s * ATT_STAGE_W;
        const uint32_t* KloW = KhiW + 2048;
        const uint32_t* VhW  = KhiW + 4096;
        const uint32_t* VlW  = KhiW + 6144;

        // ---- S = Q @ K^T (3-term bf16), frag-unit loads ----
        float sreg[8][4];
        #pragma unroll
        for (int nt = 0; nt < 8; nt++)
            #pragma unroll
            for (int c = 0; c < 4; c++) sreg[nt][c] = 0.0f;

        #pragma unroll
        for (int nt = 0; nt < 8; nt++) {
            const int j  = nt * 8 + grp;
            const int x7 = j & 7;
            const uint32_t* kh = KhiW + j * 32;
            const uint32_t* kl = KloW + j * 32;
            uint4 h0 = *(const uint4*)&kh[(u0 ^ x7) << 2];
            uint4 h1 = *(const uint4*)&kh[(u1 ^ x7) << 2];
            uint4 g0 = *(const uint4*)&kl[(u0 ^ x7) << 2];
            uint4 g1 = *(const uint4*)&kl[(u1 ^ x7) << 2];
            mma_bf16(sreg[nt], qh[0], h0.x, h0.y);
            mma_bf16(sreg[nt], qh[0], g0.x, g0.y);
            mma_bf16(sreg[nt], ql[0], h0.x, h0.y);
            mma_bf16(sreg[nt], qh[1], h0.z, h0.w);
            mma_bf16(sreg[nt], qh[1], g0.z, g0.w);
            mma_bf16(sreg[nt], ql[1], h0.z, h0.w);
            mma_bf16(sreg[nt], qh[2], h1.x, h1.y);
            mma_bf16(sreg[nt], qh[2], g1.x, g1.y);
            mma_bf16(sreg[nt], ql[2], h1.x, h1.y);
            mma_bf16(sreg[nt], qh[3], h1.z, h1.w);
            mma_bf16(sreg[nt], qh[3], g1.z, g1.w);
            mma_bf16(sreg[nt], ql[3], h1.z, h1.w);
        }

        // ---- scale + causal mask (per-warp predicate) ----
        const float scale = 0.125f;
        if (k0 + 63 > i0) {
            #pragma unroll
            for (int nt = 0; nt < 8; nt++)
                #pragma unroll
                for (int c = 0; c < 4; c++) {
                    int j = k0 + nt * 8 + 2 * qid + (c & 1);
                    int i = (c < 2) ? i0 : (i0 + 8);
                    float sv = sreg[nt][c] * scale;
                    if (j > i) sv = -1e30f;
                    sreg[nt][c] = sv;
                }
        } else {
            #pragma unroll
            for (int nt = 0; nt < 8; nt++)
                #pragma unroll
                for (int c = 0; c < 4; c++) sreg[nt][c] *= scale;
        }

        // ---- online softmax ----
        float mx0 = -1e30f, mx1 = -1e30f;
        #pragma unroll
        for (int nt = 0; nt < 8; nt++) {
            mx0 = fmaxf(mx0, fmaxf(sreg[nt][0], sreg[nt][1]));
            mx1 = fmaxf(mx1, fmaxf(sreg[nt][2], sreg[nt][3]));
        }
        #pragma unroll
        for (int off = 1; off <= 2; off <<= 1) {
            mx0 = fmaxf(mx0, __shfl_xor_sync(0xffffffffu, mx0, off));
            mx1 = fmaxf(mx1, __shfl_xor_sync(0xffffffffu, mx1, off));
        }
        float mn0 = fmaxf(m0f, mx0);
        float mn1 = fmaxf(m1f, mx1);
        float a0 = __expf(m0f - mn0);
        float a1 = __expf(m1f - mn1);
        m0f = mn0; m1f = mn1;
        #pragma unroll
        for (int nt = 0; nt < 8; nt++) {
            o[nt][0] *= a0;  o[nt][1] *= a0;
            o[nt][2] *= a1;  o[nt][3] *= a1;
        }

        // ---- exp + repack ALL P fragments first ----
        float rs0 = 0.0f, rs1 = 0.0f;
        uint32_t ph[4][4], pl[4][4];
        #pragma unroll
        for (int kc2 = 0; kc2 < 4; kc2++) {
            #pragma unroll
            for (int part = 0; part < 2; part++) {
                const int nt = kc2 * 2 + part;
                float p0 = __expf(sreg[nt][0] - mn0);
                float p1 = __expf(sreg[nt][1] - mn0);
                float p2 = __expf(sreg[nt][2] - mn1);
                float p3 = __expf(sreg[nt][3] - mn1);
                rs0 += p0 + p1;
                rs1 += p2 + p3;
                uint32_t u01 = pk_bf16(p0, p1);
                uint32_t u23 = pk_bf16(p2, p3);
                ph[kc2][2 * part]     = u01;
                ph[kc2][2 * part + 1] = u23;
                pl[kc2][2 * part]     = pk_bf16(p0 - bflo(u01), p1 - bfhi(u01));
                pl[kc2][2 * part + 1] = pk_bf16(p2 - bflo(u23), p3 - bfhi(u23));
            }
        }

        // ---- PV mma (3-term), one pass over V rows ----
        #pragma unroll
        for (int ont = 0; ont < 8; ont++) {
            const int d  = ont * 8 + grp;
            const int x7 = d & 7;
            const uint32_t* vh = VhW + d * 32;
            const uint32_t* vl = VlW + d * 32;
            uint4 h0 = *(const uint4*)&vh[(u0 ^ x7) << 2];
            uint4 h1 = *(const uint4*)&vh[(u1 ^ x7) << 2];
            uint4 g0 = *(const uint4*)&vl[(u0 ^ x7) << 2];
            uint4 g1 = *(const uint4*)&vl[(u1 ^ x7) << 2];
            mma_bf16(o[ont], ph[0], h0.x, h0.y);
            mma_bf16(o[ont], ph[0], g0.x, g0.y);
            mma_bf16(o[ont], pl[0], h0.x, h0.y);
            mma_bf16(o[ont], ph[1], h0.z, h0.w);
            mma_bf16(o[ont], ph[1], g0.z, g0.w);
            mma_bf16(o[ont], pl[1], h0.z, h0.w);
            mma_bf16(o[ont], ph[2], h1.x, h1.y);
            mma_bf16(o[ont], ph[2], g1.x, g1.y);
            mma_bf16(o[ont], pl[2], h1.x, h1.y);
            mma_bf16(o[ont], ph[3], h1.z, h1.w);
            mma_bf16(o[ont], ph[3], g1.z, g1.w);
            mma_bf16(o[ont], pl[3], h1.z, h1.w);
        }
        #pragma unroll
        for (int off = 1; off <= 2; off <<= 1) {
            rs0 += __shfl_xor_sync(0xffffffffu, rs0, off);
            rs1 += __shfl_xor_sync(0xffffffffu, rs1, off);
        }
        l0 = l0 * a0 + rs0;
        l1 = l1 * a1 + rs1;
    }

    // ---- epilogue: tf32-rounded store in FRAG-A layout (proj GEMM input) ----
    const float inv0 = 1.0f / l0;
    const float inv1 = 1.0f / l1;
    #pragma unroll
    for (int ont = 0; ont < 8; ont++) {
        #pragma unroll
        for (int c = 0; c < 4; c++) {
            int col = h * HDIM + ont * 8 + 2 * qid + (c & 1);
            int m   = b * LSEQ + i0 + ((c >> 1) << 3);
            float val = (c < 2) ? o[ont][c] * inv0 : o[ont][c] * inv1;
            int blk = (m >> 4) * (DMOD >> 3) + (col >> 3);
            int inner = ((m & 7) * 4 + (col & 3)) * 4
                      + ((col >> 2) & 1) * 2 + ((m >> 3) & 1);
            y[(size_t)blk * 128 + inner] = __uint_as_float(f2tf32(val));
        }
    }
}

// ===========================================================================
// Launch
// ===========================================================================
extern "C" void kernel_launch(void* const* d_in, const int* in_sizes, int n_in,
                              void* d_out, int out_size)
{
    (void)in_sizes; (void)n_in; (void)out_size;
    const float* x     = (const float*)d_in[0];
    const float* Wqkv  = (const float*)d_in[1];
    const float* bqkv  = (const float*)d_in[2];
    const float* Wproj = (const float*)d_in[3];
    const float* bproj = (const float*)d_in[4];
    float* out = (float*)d_out;

    float *qkvp, *yp, *xr, *wqkvr, *wprojr;
    uint32_t *kwp, *vwp;
    cudaGetSymbolAddress((void**)&qkvp, g_qkv);
    cudaGetSymbolAddress((void**)&yp, g_y);
    cudaGetSymbolAddress((void**)&xr, g_xr);
    cudaGetSymbolAddress((void**)&wqkvr, g_wqkvr);
    cudaGetSymbolAddress((void**)&wprojr, g_wprojr);
    cudaGetSymbolAddress((void**)&kwp, g_kw);
    cudaGetSymbolAddress((void**)&vwp, g_vw);

    static bool attr_set = false;
    if (!attr_set) {
        cudaFuncSetAttribute(gemm_tc, cudaFuncAttributeMaxDynamicSharedMemorySize,
                             GEMM_SMEM);
        cudaFuncSetAttribute(attn_mma, cudaFuncAttributeMaxDynamicSharedMemorySize,
                             ATTN_SMEM);
        attr_set = true;
    }

    // Pre-passes: round + relayout into fragment-major operand buffers
    {
        int nx = MROWS * DMOD;
        int nq = DMOD * NQKV;
        int np = DMOD * DMOD;
        xfrag_kernel<<<(nx + 255) / 256, 256>>>(x, xr, MROWS, DMOD);
        wfrag_kernel<<<(nq + 255) / 256, 256>>>(Wqkv, wqkvr, DMOD, NQKV);
        wfrag_kernel<<<(np + 255) / 256, 256>>>(Wproj, wprojr, DMOD, DMOD);
    }

    // QKV projection
    gemm_tc<<<dim3(NQKV / 128, MROWS / 128), 256, GEMM_SMEM>>>(
        xr, wqkvr, bqkv, qkvp, MROWS, NQKV, DMOD);
    // K/V -> frag-unit bf16 hi/lo tiles
    kvconv_kernel<<<dim3(32, 64), 128>>>(qkvp, kwp, vwp);
    // Causal flash attention, q-tile 128 (epilogue emits frag-A y)
    attn_mma<<<dim3(LSEQ / 128, BSZ * NHEAD), 256, ATTN_SMEM>>>(qkvp, kwp, vwp, yp);
    // Output projection
    gemm_tc<<<dim3(DMOD / 128, MROWS / 128), 256, GEMM_SMEM>>>(
        yp, wprojr, bproj, out, MROWS, DMOD, DMOD);
}

// round 15
// speedup vs baseline: 1.0380x; 1.0380x over previous
#include <cuda_runtime.h>
#include <cuda_bf16.h>
#include <math.h>
#include <stdint.h>

// Problem constants
#define BSZ   4
#define LSEQ  2048
#define DMOD  1024
#define NHEAD 16
#define HDIM  64
#define MROWS (BSZ * LSEQ)      // 8192
#define NQKV  (3 * DMOD)        // 3072

// Scratch (allocation-free rule: device globals)
__device__ __align__(16) float g_qkv[(size_t)MROWS * NQKV];   // [B*L, 3D] row-major
__device__ __align__(16) float g_y[(size_t)MROWS * DMOD];     // attn out, FRAG-A layout
__device__ __align__(16) float g_xr[(size_t)MROWS * DMOD];    // x rounded, FRAG-A layout
__device__ __align__(16) float g_wqkvr[(size_t)DMOD * NQKV];  // Wqkv rounded, FRAG-B
__device__ __align__(16) float g_wprojr[(size_t)DMOD * DMOD]; // Wproj rounded, FRAG-B
// Pre-converted KV: per (bh, jtile): [Khi 2048w][Klo 2048w], frag-unit tiles
__device__ __align__(16) uint32_t g_kw[(size_t)64 * 32 * 2 * 2048];
__device__ __align__(16) uint32_t g_vw[(size_t)64 * 32 * 2 * 2048];

// ===========================================================================
// Helpers
// ===========================================================================
__device__ __forceinline__ uint32_t smem_u32(const void* p) {
    uint32_t a;
    asm("{ .reg .u64 t; cvta.to.shared.u64 t, %1; cvt.u32.u64 %0, t; }"
        : "=r"(a) : "l"(p));
    return a;
}
__device__ __forceinline__ void cp_async16(uint32_t dst, const void* src) {
    asm volatile("cp.async.cg.shared.global [%0], [%1], 16;"
                 :: "r"(dst), "l"(src) : "memory");
}
__device__ __forceinline__ void cp_commit() {
    asm volatile("cp.async.commit_group;" ::: "memory");
}
#define CP_WAIT(n) asm volatile("cp.async.wait_group %0;" :: "n"(n) : "memory")

__device__ __forceinline__ uint32_t f2tf32(float f) {
    uint32_t r;
    asm("cvt.rna.tf32.f32 %0, %1;" : "=r"(r) : "f"(f));
    return r;
}
__device__ __forceinline__ void mma_tf32(float* c, const uint32_t* a, const uint32_t* b) {
    asm volatile(
        "mma.sync.aligned.m16n8k8.row.col.f32.tf32.tf32.f32 "
        "{%0,%1,%2,%3}, {%4,%5,%6,%7}, {%8,%9}, {%0,%1,%2,%3};\n"
        : "+f"(c[0]), "+f"(c[1]), "+f"(c[2]), "+f"(c[3])
        : "r"(a[0]), "r"(a[1]), "r"(a[2]), "r"(a[3]), "r"(b[0]), "r"(b[1]));
}
__device__ __forceinline__ uint32_t pk_bf16(float x, float y) {
    uint32_t r;
    asm("cvt.rn.bf16x2.f32 %0, %1, %2;" : "=r"(r) : "f"(y), "f"(x));
    return r;
}
__device__ __forceinline__ float bflo(uint32_t u) { return __uint_as_float(u << 16); }
__device__ __forceinline__ float bfhi(uint32_t u) { return __uint_as_float(u & 0xffff0000u); }

__device__ __forceinline__ void mma_bf16(float* c, const uint32_t* a,
                                         uint32_t b0, uint32_t b1) {
    asm volatile(
        "mma.sync.aligned.m16n8k16.row.col.f32.bf16.bf16.f32 "
        "{%0,%1,%2,%3}, {%4,%5,%6,%7}, {%8,%9}, {%0,%1,%2,%3};\n"
        : "+f"(c[0]), "+f"(c[1]), "+f"(c[2]), "+f"(c[3])
        : "r"(a[0]), "r"(a[1]), "r"(a[2]), "r"(a[3]), "r"(b0), "r"(b1));
}

// K/V tile word address: logical word c (2 elems each), row; unit XOR-rotated.
__device__ __forceinline__ int kaddr(int c, int row) {
    int kc = c >> 3, t = (c >> 2) & 1, q = c & 3;
    int u = q * 2 + (kc >> 1);
    int w = (kc & 1) * 2 + t;
    return row * 32 + ((u ^ (row & 7)) << 2) + w;
}

// ===========================================================================
// Fragment-major GEMM operand layouts
// ===========================================================================
__global__ void xfrag_kernel(const float* __restrict__ in, float* __restrict__ out,
                             int M, int K)
{
    int id = blockIdx.x * blockDim.x + threadIdx.x;
    if (id < M * K) {
        int m = id / K, k = id % K;
        float v = __uint_as_float(f2tf32(in[id]));
        int blk = (m >> 4) * (K >> 3) + (k >> 3);
        int inner = ((m & 7) * 4 + (k & 3)) * 4 + ((k >> 2) & 1) * 2 + ((m >> 3) & 1);
        out[(size_t)blk * 128 + inner] = v;
    }
}
__global__ void wfrag_kernel(const float* __restrict__ in, float* __restrict__ out,
                             int K, int N)
{
    int id = blockIdx.x * blockDim.x + threadIdx.x;
    if (id < K * N) {
        int k = id / N, n = id % N;
        float v = __uint_as_float(f2tf32(in[id]));
        int blk = (n >> 3) * (K >> 3) + (k >> 3);
        int inner = ((n & 7) * 4 + (k & 3)) * 2 + ((k >> 2) & 1);
        out[(size_t)blk * 64 + inner] = v;
    }
}

// ===========================================================================
// Pre-pass: K/V fp32 -> frag-unit bf16 hi/lo gmem tiles
// ===========================================================================
__global__ __launch_bounds__(128)
void kvconv_kernel(const float* __restrict__ qkv,
                   uint32_t* __restrict__ kw, uint32_t* __restrict__ vw)
{
    const int tid = threadIdx.x;
    const int jt  = blockIdx.x;
    const int bh  = blockIdx.y;
    const int b   = bh >> 4;
    const int h   = bh & 15;
    const int k0  = jt * 64;
    const float* base = qkv + (size_t)(b * LSEQ) * NQKV + h * HDIM;

    uint32_t* kh = kw + ((size_t)(bh * 32 + jt) * 2) * 2048;
    uint32_t* kl = kh + 2048;
    uint32_t* vh = vw + ((size_t)(bh * 32 + jt) * 2) * 2048;
    uint32_t* vl = vh + 2048;

    {
        const int j    = tid & 63;
        const int half = tid >> 6;
        const float* src = base + DMOD + (size_t)(k0 + j) * NQKV + half * 32;
        #pragma unroll
        for (int i = 0; i < 8; i++) {
            float4 k4 = *(const float4*)&src[4 * i];
            uint32_t h0 = pk_bf16(k4.x, k4.y);
            uint32_t h1 = pk_bf16(k4.z, k4.w);
            int c = half * 16 + 2 * i;
            kh[kaddr(c, j)]     = h0;
            kh[kaddr(c + 1, j)] = h1;
            kl[kaddr(c, j)]     = pk_bf16(k4.x - bflo(h0), k4.y - bfhi(h0));
            kl[kaddr(c + 1, j)] = pk_bf16(k4.z - bflo(h1), k4.w - bfhi(h1));
        }
    }
    {
        const int jp = tid & 31;
        const int d0 = (tid >> 5) << 4;
        const float* r0 = base + 2 * DMOD + (size_t)(k0 + 2 * jp) * NQKV + d0;
        const float* r1 = r0 + NQKV;
        #pragma unroll
        for (int i4 = 0; i4 < 4; i4++) {
            float4 x = *(const float4*)&r0[4 * i4];
            float4 yv = *(const float4*)&r1[4 * i4];
            float xs[4] = {x.x, x.y, x.z, x.w};
            float ys[4] = {yv.x, yv.y, yv.z, yv.w};
            #pragma unroll
            for (int e = 0; e < 4; e++) {
                int d = d0 + 4 * i4 + e;
                uint32_t hi = pk_bf16(xs[e], ys[e]);
                vh[kaddr(jp, d)] = hi;
                vl[kaddr(jp, d)] = pk_bf16(xs[e] - bflo(hi), ys[e] - bfhi(hi));
            }
        }
    }
}

// ===========================================================================
// tf32 tensor-core GEMM + bias, FRAG-MAJOR A/B inputs.
// Round-15: 6-stage pipeline, 2 chunks processed per barrier (32 barriers).
// Hazard: loads for chunks c+4/c+5 -> stages (c-2)%6/(c-1)%6, last read in
// the previous iteration and gated by this iteration's __syncthreads.
// ===========================================================================
#define GSTAGES 6
#define GBK 16
#define A_STAGE_B 8192
#define B_STAGE_B 8192
#define ST_B (A_STAGE_B + B_STAGE_B)
#define GEMM_SMEM (GSTAGES * ST_B)    // 98304

__global__ __launch_bounds__(256, 2)
void gemm_tc(const float* __restrict__ A, const float* __restrict__ W,
             const float* __restrict__ bias, float* __restrict__ C,
             int M, int N, int K)
{
    extern __shared__ __align__(16) float sm_f[];
    const uint32_t sm_b = smem_u32(sm_f);

    const int tid  = threadIdx.x;
    const int wid  = tid >> 5;
    const int lane = tid & 31;
    const int grp  = lane >> 2;
    const int qid  = lane & 3;
    const int wm   = wid >> 2;
    const int wn   = wid & 3;
    const int m0   = blockIdx.y * 128;
    const int n0   = blockIdx.x * 128;
    const int NCHUNK = K / GBK;
    const int KB = K >> 3;

    float acc[4][4][4];
    #pragma unroll
    for (int mi = 0; mi < 4; mi++)
        #pragma unroll
        for (int ni = 0; ni < 4; ni++)
            #pragma unroll
            for (int q = 0; q < 4; q++) acc[mi][ni][q] = 0.0f;

    auto load_stage = [&](int s, int kc0) {
        const uint32_t as = sm_b + s * ST_B;
        const uint32_t bs = as + A_STAGE_B;
        const int kb = kc0 >> 3;
        #pragma unroll
        for (int i = 0; i < 2; i++) {
            int id   = tid + i * 256;
            int mblk = id >> 6;
            int off  = id & 63;
            const float* src = A + ((size_t)((m0 >> 4) + mblk) * KB + kb) * 128 + off * 4;
            cp_async16(as + mblk * 1024 + off * 16, src);
        }
        #pragma unroll
        for (int i = 0; i < 2; i++) {
            int id   = tid + i * 256;
            int nblk = id >> 5;
            int off  = id & 31;
            const float* src = W + ((size_t)((n0 >> 3) + nblk) * KB + kb) * 64 + off * 4;
            cp_async16(bs + nblk * 512 + off * 16, src);
        }
        cp_commit();
    };

    auto do_chunk = [&](int c) {
        const float* as = sm_f + (c % GSTAGES) * (ST_B / 4);
        const float* bs = as + A_STAGE_B / 4;
        #pragma unroll
        for (int ks = 0; ks < 2; ks++) {
            uint32_t af[4][4], bf[4][2];
            #pragma unroll
            for (int mi = 0; mi < 4; mi++) {
                const float4 fa = *(const float4*)
                    &as[((wm * 4 + mi) * 2 + ks) * 128 + lane * 4];
                af[mi][0] = __float_as_uint(fa.x);
                af[mi][1] = __float_as_uint(fa.y);
                af[mi][2] = __float_as_uint(fa.z);
                af[mi][3] = __float_as_uint(fa.w);
            }
            #pragma unroll
            for (int ni = 0; ni < 4; ni++) {
                const float2 fb = *(const float2*)
                    &bs[((wn * 4 + ni) * 2 + ks) * 64 + lane * 2];
                bf[ni][0] = __float_as_uint(fb.x);
                bf[ni][1] = __float_as_uint(fb.y);
            }
            #pragma unroll
            for (int mi = 0; mi < 4; mi++)
                #pragma unroll
                for (int ni = 0; ni < 4; ni++)
                    mma_tf32(acc[mi][ni], af[mi], bf[ni]);
        }
    };

    // Prologue: 4 chunks in flight (4 groups)
    #pragma unroll
    for (int s = 0; s < 4; s++) load_stage(s, s * GBK);

    for (int c = 0; c < NCHUNK; c += 2) {
        CP_WAIT(2);          // chunks c, c+1 resident (<=2 groups pending)
        __syncthreads();     // closes previous iteration's reads
        if (c + 4 < NCHUNK) load_stage((c + 4) % GSTAGES, (c + 4) * GBK);
        if (c + 5 < NCHUNK) load_stage((c + 5) % GSTAGES, (c + 5) * GBK);
        do_chunk(c);
        do_chunk(c + 1);
    }

    #pragma unroll
    for (int mi = 0; mi < 4; mi++) {
        int r0 = m0 + wm * 64 + mi * 16 + grp;
        #pragma unroll
        for (int ni = 0; ni < 4; ni++) {
            int col = n0 + wn * 32 + ni * 8 + qid * 2;
            float2 bv = *(const float2*)&bias[col];
            float2 o0, o1;
            o0.x = acc[mi][ni][0] + bv.x;  o0.y = acc[mi][ni][1] + bv.y;
            o1.x = acc[mi][ni][2] + bv.x;  o1.y = acc[mi][ni][3] + bv.y;
            *(float2*)&C[(size_t)r0 * N + col]       = o0;
            *(float2*)&C[(size_t)(r0 + 8) * N + col] = o1;
        }
    }
}

// ===========================================================================
// Flash-attention (causal), bf16 3-term mma.sync; frag-unit K/V tiles.
// Round-15: reverted to round-13 config (128 thr, 3 CTAs/SM, q-tile 64) —
// the 256-thread variant spilled under the 128-reg clamp and regressed.
// ===========================================================================
#define ATT_STAGE_W 8192
#define ATTN_SMEM (2 * ATT_STAGE_W * 4)   // 65536 B

__global__ __launch_bounds__(128, 3)
void attn_mma(const float* __restrict__ qkv,
              const uint32_t* __restrict__ kw, const uint32_t* __restrict__ vw,
              float* __restrict__ y)
{
    extern __shared__ __align__(16) uint32_t sm_w[];
    const uint32_t sm_b = smem_u32(sm_w);

    const int tid  = threadIdx.x;
    const int wid  = tid >> 5;
    const int lane = tid & 31;
    const int grp  = lane >> 2;
    const int qid  = lane & 3;

    const int qt = gridDim.x - 1 - blockIdx.x;
    const int bh = blockIdx.y;
    const int b  = bh >> 4;
    const int h  = bh & 15;
    const int q0 = qt * 64;

    const float* base = qkv + (size_t)(b * LSEQ) * NQKV + h * HDIM;
    const char* gk_base = (const char*)(kw + (size_t)bh * 32 * 2 * 2048);
    const char* gv_base = (const char*)(vw + (size_t)bh * 32 * 2 * 2048);

    // ---- Q fragments (hi/lo bf16) ----
    uint32_t qh[4][4], ql[4][4];
    const int i0 = q0 + wid * 16 + grp;
    #pragma unroll
    for (int kc = 0; kc < 4; kc++)
        #pragma unroll
        for (int hh = 0; hh < 2; hh++)
            #pragma unroll
            for (int rr = 0; rr < 2; rr++) {
                const float* p = base + (size_t)(i0 + 8 * rr) * NQKV
                               + kc * 16 + hh * 8 + 2 * qid;
                float2 v = *(const float2*)p;
                uint32_t hi = pk_bf16(v.x, v.y);
                qh[kc][2 * hh + rr] = hi;
                ql[kc][2 * hh + rr] = pk_bf16(v.x - bflo(hi), v.y - bfhi(hi));
            }

    float o[8][4];
    #pragma unroll
    for (int nt = 0; nt < 8; nt++)
        #pragma unroll
        for (int c = 0; c < 4; c++) o[nt][c] = 0.0f;
    float m0f = -1e30f, m1f = -1e30f, l0 = 0.0f, l1 = 0.0f;

    auto prefetch = [&](int kt, int s) {
        const char* gk = gk_base + (size_t)kt * 16384;
        const char* gv = gv_base + (size_t)kt * 16384;
        const uint32_t dst = sm_b + s * (ATT_STAGE_W * 4);
        #pragma unroll
        for (int i = 0; i < 16; i++) {
            int id = tid + i * 128;
            const char* src = (id < 1024) ? (gk + id * 16)
                                          : (gv + (id - 1024) * 16);
            cp_async16(dst + id * 16, src);
        }
        cp_commit();
    };

    prefetch(0, 0);

    const int u0 = qid * 2;
    const int u1 = qid * 2 + 1;

    for (int kt = 0; kt <= qt; kt++) {
        const int k0 = kt * 64;
        const int s  = kt & 1;
        CP_WAIT(0);
        __syncthreads();
        if (kt < qt) prefetch(kt + 1, s ^ 1);

        const uint32_t* KhiW = sm_w + s * ATT_STAGE_W;
        const uint32_t* KloW = KhiW + 2048;
        const uint32_t* VhW  = KhiW + 4096;
        const uint32_t* VlW  = KhiW + 6144;

        // ---- S = Q @ K^T (3-term bf16), frag-unit loads ----
        float sreg[8][4];
        #pragma unroll
        for (int nt = 0; nt < 8; nt++)
            #pragma unroll
            for (int c = 0; c < 4; c++) sreg[nt][c] = 0.0f;

        #pragma unroll
        for (int nt = 0; nt < 8; nt++) {
            const int j  = nt * 8 + grp;
            const int x7 = j & 7;
            const uint32_t* kh = KhiW + j * 32;
            const uint32_t* kl = KloW + j * 32;
            uint4 h0 = *(const uint4*)&kh[(u0 ^ x7) << 2];
            uint4 h1 = *(const uint4*)&kh[(u1 ^ x7) << 2];
            uint4 g0 = *(const uint4*)&kl[(u0 ^ x7) << 2];
            uint4 g1 = *(const uint4*)&kl[(u1 ^ x7) << 2];
            mma_bf16(sreg[nt], qh[0], h0.x, h0.y);
            mma_bf16(sreg[nt], qh[0], g0.x, g0.y);
            mma_bf16(sreg[nt], ql[0], h0.x, h0.y);
            mma_bf16(sreg[nt], qh[1], h0.z, h0.w);
            mma_bf16(sreg[nt], qh[1], g0.z, g0.w);
            mma_bf16(sreg[nt], ql[1], h0.z, h0.w);
            mma_bf16(sreg[nt], qh[2], h1.x, h1.y);
            mma_bf16(sreg[nt], qh[2], g1.x, g1.y);
            mma_bf16(sreg[nt], ql[2], h1.x, h1.y);
            mma_bf16(sreg[nt], qh[3], h1.z, h1.w);
            mma_bf16(sreg[nt], qh[3], g1.z, g1.w);
            mma_bf16(sreg[nt], ql[3], h1.z, h1.w);
        }

        // ---- scale + causal mask ----
        const float scale = 0.125f;
        if (kt == qt) {
            #pragma unroll
            for (int nt = 0; nt < 8; nt++)
                #pragma unroll
                for (int c = 0; c < 4; c++) {
                    int j = k0 + nt * 8 + 2 * qid + (c & 1);
                    int i = (c < 2) ? i0 : (i0 + 8);
                    float sv = sreg[nt][c] * scale;
                    if (j > i) sv = -1e30f;
                    sreg[nt][c] = sv;
                }
        } else {
            #pragma unroll
            for (int nt = 0; nt < 8; nt++)
                #pragma unroll
                for (int c = 0; c < 4; c++) sreg[nt][c] *= scale;
        }

        // ---- online softmax ----
        float mx0 = -1e30f, mx1 = -1e30f;
        #pragma unroll
        for (int nt = 0; nt < 8; nt++) {
            mx0 = fmaxf(mx0, fmaxf(sreg[nt][0], sreg[nt][1]));
            mx1 = fmaxf(mx1, fmaxf(sreg[nt][2], sreg[nt][3]));
        }
        #pragma unroll
        for (int off = 1; off <= 2; off <<= 1) {
            mx0 = fmaxf(mx0, __shfl_xor_sync(0xffffffffu, mx0, off));
            mx1 = fmaxf(mx1, __shfl_xor_sync(0xffffffffu, mx1, off));
        }
        float mn0 = fmaxf(m0f, mx0);
        float mn1 = fmaxf(m1f, mx1);
        float a0 = __expf(m0f - mn0);
        float a1 = __expf(m1f - mn1);
        m0f = mn0; m1f = mn1;
        #pragma unroll
        for (int nt = 0; nt < 8; nt++) {
            o[nt][0] *= a0;  o[nt][1] *= a0;
            o[nt][2] *= a1;  o[nt][3] *= a1;
        }

        // ---- exp + repack ALL P fragments first ----
        float rs0 = 0.0f, rs1 = 0.0f;
        uint32_t ph[4][4], pl[4][4];
        #pragma unroll
        for (int kc2 = 0; kc2 < 4; kc2++) {
            #pragma unroll
            for (int part = 0; part < 2; part++) {
                const int nt = kc2 * 2 + part;
                float p0 = __expf(sreg[nt][0] - mn0);
                float p1 = __expf(sreg[nt][1] - mn0);
                float p2 = __expf(sreg[nt][2] - mn1);
                float p3 = __expf(sreg[nt][3] - mn1);
                rs0 += p0 + p1;
                rs1 += p2 + p3;
                uint32_t u01 = pk_bf16(p0, p1);
                uint32_t u23 = pk_bf16(p2, p3);
                ph[kc2][2 * part]     = u01;
                ph[kc2][2 * part + 1] = u23;
                pl[kc2][2 * part]     = pk_bf16(p0 - bflo(u01), p1 - bfhi(u01));
                pl[kc2][2 * part + 1] = pk_bf16(p2 - bflo(u23), p3 - bfhi(u23));
            }
        }

        // ---- PV mma (3-term), one pass over V rows ----
        #pragma unroll
        for (int ont = 0; ont < 8; ont++) {
            const int d  = ont * 8 + grp;
            const int x7 = d & 7;
            const uint32_t* vh = VhW + d * 32;
            const uint32_t* vl = VlW + d * 32;
            uint4 h0 = *(const uint4*)&vh[(u0 ^ x7) << 2];
            uint4 h1 = *(const uint4*)&vh[(u1 ^ x7) << 2];
            uint4 g0 = *(const uint4*)&vl[(u0 ^ x7) << 2];
            uint4 g1 = *(const uint4*)&vl[(u1 ^ x7) << 2];
            mma_bf16(o[ont], ph[0], h0.x, h0.y);
            mma_bf16(o[ont], ph[0], g0.x, g0.y);
            mma_bf16(o[ont], pl[0], h0.x, h0.y);
            mma_bf16(o[ont], ph[1], h0.z, h0.w);
            mma_bf16(o[ont], ph[1], g0.z, g0.w);
            mma_bf16(o[ont], pl[1], h0.z, h0.w);
            mma_bf16(o[ont], ph[2], h1.x, h1.y);
            mma_bf16(o[ont], ph[2], g1.x, g1.y);
            mma_bf16(o[ont], pl[2], h1.x, h1.y);
            mma_bf16(o[ont], ph[3], h1.z, h1.w);
            mma_bf16(o[ont], ph[3], g1.z, g1.w);
            mma_bf16(o[ont], pl[3], h1.z, h1.w);
        }
        #pragma unroll
        for (int off = 1; off <= 2; off <<= 1) {
            rs0 += __shfl_xor_sync(0xffffffffu, rs0, off);
            rs1 += __shfl_xor_sync(0xffffffffu, rs1, off);
        }
        l0 = l0 * a0 + rs0;
        l1 = l1 * a1 + rs1;
    }

    // ---- epilogue: tf32-rounded store in FRAG-A layout (proj GEMM input) ----
    const float inv0 = 1.0f / l0;
    const float inv1 = 1.0f / l1;
    #pragma unroll
    for (int ont = 0; ont < 8; ont++) {
        #pragma unroll
        for (int c = 0; c < 4; c++) {
            int col = h * HDIM + ont * 8 + 2 * qid + (c & 1);
            int m   = b * LSEQ + i0 + ((c >> 1) << 3);
            float val = (c < 2) ? o[ont][c] * inv0 : o[ont][c] * inv1;
            int blk = (m >> 4) * (DMOD >> 3) + (col >> 3);
            int inner = ((m & 7) * 4 + (col & 3)) * 4
                      + ((col >> 2) & 1) * 2 + ((m >> 3) & 1);
            y[(size_t)blk * 128 + inner] = __uint_as_float(f2tf32(val));
        }
    }
}

// ===========================================================================
// Launch
// ===========================================================================
extern "C" void kernel_launch(void* const* d_in, const int* in_sizes, int n_in,
                              void* d_out, int out_size)
{
    (void)in_sizes; (void)n_in; (void)out_size;
    const float* x     = (const float*)d_in[0];
    const float* Wqkv  = (const float*)d_in[1];
    const float* bqkv  = (const float*)d_in[2];
    const float* Wproj = (const float*)d_in[3];
    const float* bproj = (const float*)d_in[4];
    float* out = (float*)d_out;

    float *qkvp, *yp, *xr, *wqkvr, *wprojr;
    uint32_t *kwp, *vwp;
    cudaGetSymbolAddress((void**)&qkvp, g_qkv);
    cudaGetSymbolAddress((void**)&yp, g_y);
    cudaGetSymbolAddress((void**)&xr, g_xr);
    cudaGetSymbolAddress((void**)&wqkvr, g_wqkvr);
    cudaGetSymbolAddress((void**)&wprojr, g_wprojr);
    cudaGetSymbolAddress((void**)&kwp, g_kw);
    cudaGetSymbolAddress((void**)&vwp, g_vw);

    static bool attr_set = false;
    if (!attr_set) {
        cudaFuncSetAttribute(gemm_tc, cudaFuncAttributeMaxDynamicSharedMemorySize,
                             GEMM_SMEM);
        cudaFuncSetAttribute(attn_mma, cudaFuncAttributeMaxDynamicSharedMemorySize,
                             ATTN_SMEM);
        attr_set = true;
    }

    // Pre-passes: round + relayout into fragment-major operand buffers
    {
        int nx = MROWS * DMOD;
        int nq = DMOD * NQKV;
        int np = DMOD * DMOD;
        xfrag_kernel<<<(nx + 255) / 256, 256>>>(x, xr, MROWS, DMOD);
        wfrag_kernel<<<(nq + 255) / 256, 256>>>(Wqkv, wqkvr, DMOD, NQKV);
        wfrag_kernel<<<(np + 255) / 256, 256>>>(Wproj, wprojr, DMOD, DMOD);
    }

    // QKV projection
    gemm_tc<<<dim3(NQKV / 128, MROWS / 128), 256, GEMM_SMEM>>>(
        xr, wqkvr, bqkv, qkvp, MROWS, NQKV, DMOD);
    // K/V -> frag-unit bf16 hi/lo tiles
    kvconv_kernel<<<dim3(32, 64), 128>>>(qkvp, kwp, vwp);
    // Causal flash attention (q-tile 64, 128 threads, 3 CTAs/SM)
    attn_mma<<<dim3(LSEQ / 64, BSZ * NHEAD), 128, ATTN_SMEM>>>(qkvp, kwp, vwp, yp);
    // Output projection
    gemm_tc<<<dim3(DMOD / 128, MROWS / 128), 256, GEMM_SMEM>>>(
        yp, wprojr, bproj, out, MROWS, DMOD, DMOD);
}

// round 17
// speedup vs baseline: 1.0928x; 1.0527x over previous
#include <cuda_runtime.h>
#include <cuda_bf16.h>
#include <math.h>
#include <stdint.h>

// Problem constants
#define BSZ   4
#define LSEQ  2048
#define DMOD  1024
#define NHEAD 16
#define HDIM  64
#define MROWS (BSZ * LSEQ)      // 8192
#define NQKV  (3 * DMOD)        // 3072

// Scratch (allocation-free rule: device globals)
__device__ __align__(16) float g_qkv[(size_t)MROWS * NQKV];   // [B*L, 3D] row-major
__device__ __align__(16) float g_y[(size_t)MROWS * DMOD];     // attn out, FRAG-A layout
__device__ __align__(16) float g_xr[(size_t)MROWS * DMOD];    // x rounded, FRAG-A layout
__device__ __align__(16) float g_wqkvr[(size_t)DMOD * NQKV];  // Wqkv rounded, FRAG-B
__device__ __align__(16) float g_wprojr[(size_t)DMOD * DMOD]; // Wproj rounded, FRAG-B
// Pre-converted KV: per (bh, jtile): [Khi 2048w][Klo 2048w], frag-unit tiles
__device__ __align__(16) uint32_t g_kw[(size_t)64 * 32 * 2 * 2048];
__device__ __align__(16) uint32_t g_vw[(size_t)64 * 32 * 2 * 2048];

// ===========================================================================
// Helpers
// ===========================================================================
__device__ __forceinline__ uint32_t smem_u32(const void* p) {
    uint32_t a;
    asm("{ .reg .u64 t; cvta.to.shared.u64 t, %1; cvt.u32.u64 %0, t; }"
        : "=r"(a) : "l"(p));
    return a;
}
__device__ __forceinline__ void cp_async16(uint32_t dst, const void* src) {
    asm volatile("cp.async.cg.shared.global [%0], [%1], 16;"
                 :: "r"(dst), "l"(src) : "memory");
}
__device__ __forceinline__ void cp_commit() {
    asm volatile("cp.async.commit_group;" ::: "memory");
}
#define CP_WAIT(n) asm volatile("cp.async.wait_group %0;" :: "n"(n) : "memory")

__device__ __forceinline__ uint32_t f2tf32(float f) {
    uint32_t r;
    asm("cvt.rna.tf32.f32 %0, %1;" : "=r"(r) : "f"(f));
    return r;
}
__device__ __forceinline__ void mma_tf32(float* c, const uint32_t* a, const uint32_t* b) {
    asm volatile(
        "mma.sync.aligned.m16n8k8.row.col.f32.tf32.tf32.f32 "
        "{%0,%1,%2,%3}, {%4,%5,%6,%7}, {%8,%9}, {%0,%1,%2,%3};\n"
        : "+f"(c[0]), "+f"(c[1]), "+f"(c[2]), "+f"(c[3])
        : "r"(a[0]), "r"(a[1]), "r"(a[2]), "r"(a[3]), "r"(b[0]), "r"(b[1]));
}
__device__ __forceinline__ uint32_t pk_bf16(float x, float y) {
    uint32_t r;
    asm("cvt.rn.bf16x2.f32 %0, %1, %2;" : "=r"(r) : "f"(y), "f"(x));
    return r;
}
__device__ __forceinline__ float bflo(uint32_t u) { return __uint_as_float(u << 16); }
__device__ __forceinline__ float bfhi(uint32_t u) { return __uint_as_float(u & 0xffff0000u); }

__device__ __forceinline__ void mma_bf16(float* c, const uint32_t* a,
                                         uint32_t b0, uint32_t b1) {
    asm volatile(
        "mma.sync.aligned.m16n8k16.row.col.f32.bf16.bf16.f32 "
        "{%0,%1,%2,%3}, {%4,%5,%6,%7}, {%8,%9}, {%0,%1,%2,%3};\n"
        : "+f"(c[0]), "+f"(c[1]), "+f"(c[2]), "+f"(c[3])
        : "r"(a[0]), "r"(a[1]), "r"(a[2]), "r"(a[3]), "r"(b0), "r"(b1));
}

// K/V tile word address: logical word c (2 elems each), row; unit XOR-rotated.
__device__ __forceinline__ int kaddr(int c, int row) {
    int kc = c >> 3, t = (c >> 2) & 1, q = c & 3;
    int u = q * 2 + (kc >> 1);
    int w = (kc & 1) * 2 + t;
    return row * 32 + ((u ^ (row & 7)) << 2) + w;
}

// ===========================================================================
// Fragment-major GEMM operand layouts — warp-per-block, coalesced stores.
// ===========================================================================
__global__ __launch_bounds__(256)
void xfrag_kernel(const float* __restrict__ in, float* __restrict__ out,
                  int M, int K)
{
    const int wid  = threadIdx.x >> 5;
    const int lane = threadIdx.x & 31;
    const int bid  = blockIdx.x * 8 + wid;
    const int KB   = K >> 3;
    const int m0   = (bid / KB) << 4;
    const int k0   = (bid % KB) << 3;
    float v[4];
    #pragma unroll
    for (int w = 0; w < 4; w++) {
        int m = m0 + ((w & 1) << 3) + (lane >> 2);
        int k = k0 + (lane & 3) + ((w >> 1) << 2);
        v[w] = __uint_as_float(f2tf32(in[(size_t)m * K + k]));
    }
    *(float4*)&out[(size_t)bid * 128 + lane * 4] =
        make_float4(v[0], v[1], v[2], v[3]);
}
__global__ __launch_bounds__(256)
void wfrag_kernel(const float* __restrict__ in, float* __restrict__ out,
                  int K, int N)
{
    const int wid  = threadIdx.x >> 5;
    const int lane = threadIdx.x & 31;
    const int bid  = blockIdx.x * 8 + wid;
    const int KB   = K >> 3;
    const int n0   = (bid / KB) << 3;
    const int k0   = (bid % KB) << 3;
    float v[2];
    #pragma unroll
    for (int e = 0; e < 2; e++) {
        int n = n0 + (lane >> 2);
        int k = k0 + (lane & 3) + (e << 2);
        v[e] = __uint_as_float(f2tf32(in[(size_t)k * N + n]));
    }
    *(float2*)&out[(size_t)bid * 64 + lane * 2] = make_float2(v[0], v[1]);
}

// ===========================================================================
// Pre-pass: K/V fp32 -> frag-unit bf16 hi/lo gmem tiles (smem-staged stores)
// ===========================================================================
__global__ __launch_bounds__(128)
void kvconv_kernel(const float* __restrict__ qkv,
                   uint32_t* __restrict__ kw, uint32_t* __restrict__ vw)
{
    __shared__ __align__(16) uint32_t st[8192];   // [Khi 2048][Klo 2048][Vhi][Vlo]
    uint32_t* khS = st;
    uint32_t* klS = st + 2048;
    uint32_t* vhS = st + 4096;
    uint32_t* vlS = st + 6144;

    const int tid = threadIdx.x;
    const int jt  = blockIdx.x;
    const int bh  = blockIdx.y;
    const int b   = bh >> 4;
    const int h   = bh & 15;
    const int k0  = jt * 64;
    const float* base = qkv + (size_t)(b * LSEQ) * NQKV + h * HDIM;

    {
        const int j    = tid & 63;
        const int half = tid >> 6;
        const float* src = base + DMOD + (size_t)(k0 + j) * NQKV + half * 32;
        #pragma unroll
        for (int i = 0; i < 8; i++) {
            float4 k4 = *(const float4*)&src[4 * i];
            uint32_t h0 = pk_bf16(k4.x, k4.y);
            uint32_t h1 = pk_bf16(k4.z, k4.w);
            int c = half * 16 + 2 * i;
            khS[kaddr(c, j)]     = h0;
            khS[kaddr(c + 1, j)] = h1;
            klS[kaddr(c, j)]     = pk_bf16(k4.x - bflo(h0), k4.y - bfhi(h0));
            klS[kaddr(c + 1, j)] = pk_bf16(k4.z - bflo(h1), k4.w - bfhi(h1));
        }
    }
    {
        const int jp = tid & 31;
        const int d0 = (tid >> 5) << 4;
        const float* r0 = base + 2 * DMOD + (size_t)(k0 + 2 * jp) * NQKV + d0;
        const float* r1 = r0 + NQKV;
        #pragma unroll
        for (int i4 = 0; i4 < 4; i4++) {
            float4 x = *(const float4*)&r0[4 * i4];
            float4 yv = *(const float4*)&r1[4 * i4];
            float xs[4] = {x.x, x.y, x.z, x.w};
            float ys[4] = {yv.x, yv.y, yv.z, yv.w};
            #pragma unroll
            for (int e = 0; e < 4; e++) {
                int d = d0 + 4 * i4 + e;
                uint32_t hi = pk_bf16(xs[e], ys[e]);
                vhS[kaddr(jp, d)] = hi;
                vlS[kaddr(jp, d)] = pk_bf16(xs[e] - bflo(hi), ys[e] - bfhi(hi));
            }
        }
    }
    __syncthreads();

    uint32_t* kG = kw + ((size_t)(bh * 32 + jt) * 2) * 2048;
    uint32_t* vG = vw + ((size_t)(bh * 32 + jt) * 2) * 2048;
    #pragma unroll
    for (int i = 0; i < 8; i++) {
        int w = (tid + i * 128) * 4;
        *(uint4*)&kG[w] = *(const uint4*)&st[w];
        *(uint4*)&vG[w] = *(const uint4*)&st[4096 + w];
    }
}

// ===========================================================================
// tf32 tensor-core GEMM + bias, FRAG-MAJOR A/B inputs (6-stage, 2 chunks/bar)
// ===========================================================================
#define GSTAGES 6
#define GBK 16
#define A_STAGE_B 8192
#define B_STAGE_B 8192
#define ST_B (A_STAGE_B + B_STAGE_B)
#define GEMM_SMEM (GSTAGES * ST_B)    // 98304

__global__ __launch_bounds__(256, 2)
void gemm_tc(const float* __restrict__ A, const float* __restrict__ W,
             const float* __restrict__ bias, float* __restrict__ C,
             int M, int N, int K)
{
    extern __shared__ __align__(16) float sm_f[];
    const uint32_t sm_b = smem_u32(sm_f);

    const int tid  = threadIdx.x;
    const int wid  = tid >> 5;
    const int lane = tid & 31;
    const int grp  = lane >> 2;
    const int qid  = lane & 3;
    const int wm   = wid >> 2;
    const int wn   = wid & 3;
    const int m0   = blockIdx.y * 128;
    const int n0   = blockIdx.x * 128;
    const int NCHUNK = K / GBK;
    const int KB = K >> 3;

    float acc[4][4][4];
    #pragma unroll
    for (int mi = 0; mi < 4; mi++)
        #pragma unroll
        for (int ni = 0; ni < 4; ni++)
            #pragma unroll
            for (int q = 0; q < 4; q++) acc[mi][ni][q] = 0.0f;

    auto load_stage = [&](int s, int kc0) {
        const uint32_t as = sm_b + s * ST_B;
        const uint32_t bs = as + A_STAGE_B;
        const int kb = kc0 >> 3;
        #pragma unroll
        for (int i = 0; i < 2; i++) {
            int id   = tid + i * 256;
            int mblk = id >> 6;
            int off  = id & 63;
            const float* src = A + ((size_t)((m0 >> 4) + mblk) * KB + kb) * 128 + off * 4;
            cp_async16(as + mblk * 1024 + off * 16, src);
        }
        #pragma unroll
        for (int i = 0; i < 2; i++) {
            int id   = tid + i * 256;
            int nblk = id >> 5;
            int off  = id & 31;
            const float* src = W + ((size_t)((n0 >> 3) + nblk) * KB + kb) * 64 + off * 4;
            cp_async16(bs + nblk * 512 + off * 16, src);
        }
        cp_commit();
    };

    auto do_chunk = [&](int c) {
        const float* as = sm_f + (c % GSTAGES) * (ST_B / 4);
        const float* bs = as + A_STAGE_B / 4;
        #pragma unroll
        for (int ks = 0; ks < 2; ks++) {
            uint32_t af[4][4], bf[4][2];
            #pragma unroll
            for (int mi = 0; mi < 4; mi++) {
                const float4 fa = *(const float4*)
                    &as[((wm * 4 + mi) * 2 + ks) * 128 + lane * 4];
                af[mi][0] = __float_as_uint(fa.x);
                af[mi][1] = __float_as_uint(fa.y);
                af[mi][2] = __float_as_uint(fa.z);
                af[mi][3] = __float_as_uint(fa.w);
            }
            #pragma unroll
            for (int ni = 0; ni < 4; ni++) {
                const float2 fb = *(const float2*)
                    &bs[((wn * 4 + ni) * 2 + ks) * 64 + lane * 2];
                bf[ni][0] = __float_as_uint(fb.x);
                bf[ni][1] = __float_as_uint(fb.y);
            }
            #pragma unroll
            for (int mi = 0; mi < 4; mi++)
                #pragma unroll
                for (int ni = 0; ni < 4; ni++)
                    mma_tf32(acc[mi][ni], af[mi], bf[ni]);
        }
    };

    #pragma unroll
    for (int s = 0; s < 4; s++) load_stage(s, s * GBK);

    for (int c = 0; c < NCHUNK; c += 2) {
        CP_WAIT(2);
        __syncthreads();
        if (c + 4 < NCHUNK) load_stage((c + 4) % GSTAGES, (c + 4) * GBK);
        if (c + 5 < NCHUNK) load_stage((c + 5) % GSTAGES, (c + 5) * GBK);
        do_chunk(c);
        do_chunk(c + 1);
    }

    #pragma unroll
    for (int mi = 0; mi < 4; mi++) {
        int r0 = m0 + wm * 64 + mi * 16 + grp;
        #pragma unroll
        for (int ni = 0; ni < 4; ni++) {
            int col = n0 + wn * 32 + ni * 8 + qid * 2;
            float2 bv = *(const float2*)&bias[col];
            float2 o0, o1;
            o0.x = acc[mi][ni][0] + bv.x;  o0.y = acc[mi][ni][1] + bv.y;
            o1.x = acc[mi][ni][2] + bv.x;  o1.y = acc[mi][ni][3] + bv.y;
            *(float2*)&C[(size_t)r0 * N + col]       = o0;
            *(float2*)&C[(size_t)(r0 + 8) * N + col] = o1;
        }
    }
}

// ===========================================================================
// Flash-attention (causal), bf16 3-term mma.sync; frag-unit K/V tiles.
// (128 thr, 3 CTAs/SM, q-tile 64)
// ===========================================================================
#define ATT_STAGE_W 8192
#define ATTN_SMEM (2 * ATT_STAGE_W * 4)   // 65536 B

__global__ __launch_bounds__(128, 3)
void attn_mma(const float* __restrict__ qkv,
              const uint32_t* __restrict__ kw, const uint32_t* __restrict__ vw,
              float* __restrict__ y)
{
    extern __shared__ __align__(16) uint32_t sm_w[];
    const uint32_t sm_b = smem_u32(sm_w);

    const int tid  = threadIdx.x;
    const int wid  = tid >> 5;
    const int lane = tid & 31;
    const int grp  = lane >> 2;
    const int qid  = lane & 3;

    const int qt = gridDim.x - 1 - blockIdx.x;
    const int bh = blockIdx.y;
    const int b  = bh >> 4;
    const int h  = bh & 15;
    const int q0 = qt * 64;

    const float* base = qkv + (size_t)(b * LSEQ) * NQKV + h * HDIM;
    const char* gk_base = (const char*)(kw + (size_t)bh * 32 * 2 * 2048);
    const char* gv_base = (const char*)(vw + (size_t)bh * 32 * 2 * 2048);

    // ---- Q fragments (hi/lo bf16) ----
    uint32_t qh[4][4], ql[4][4];
    const int i0 = q0 + wid * 16 + grp;
    #pragma unroll
    for (int kc = 0; kc < 4; kc++)
        #pragma unroll
        for (int hh = 0; hh < 2; hh++)
            #pragma unroll
            for (int rr = 0; rr < 2; rr++) {
                const float* p = base + (size_t)(i0 + 8 * rr) * NQKV
                               + kc * 16 + hh * 8 + 2 * qid;
                float2 v = *(const float2*)p;
                uint32_t hi = pk_bf16(v.x, v.y);
                qh[kc][2 * hh + rr] = hi;
                ql[kc][2 * hh + rr] = pk_bf16(v.x - bflo(hi), v.y - bfhi(hi));
            }

    float o[8][4];
    #pragma unroll
    for (int nt = 0; nt < 8; nt++)
        #pragma unroll
        for (int c = 0; c < 4; c++) o[nt][c] = 0.0f;
    float m0f = -1e30f, m1f = -1e30f, l0 = 0.0f, l1 = 0.0f;

    auto prefetch = [&](int kt, int s) {
        const char* gk = gk_base + (size_t)kt * 16384;
        const char* gv = gv_base + (size_t)kt * 16384;
        const uint32_t dst = sm_b + s * (ATT_STAGE_W * 4);
        #pragma unroll
        for (int i = 0; i < 16; i++) {
            int id = tid + i * 128;
            const char* src = (id < 1024) ? (gk + id * 16)
                                          : (gv + (id - 1024) * 16);
            cp_async16(dst + id * 16, src);
        }
        cp_commit();
    };

    prefetch(0, 0);

    const int u0 = qid * 2;
    const int u1 = qid * 2 + 1;

    for (int kt = 0; kt <= qt; kt++) {
        const int k0 = kt * 64;
        const int s  = kt & 1;
        CP_WAIT(0);
        __syncthreads();
        if (kt < qt) prefetch(kt + 1, s ^ 1);

        const uint32_t* KhiW = sm_w + s * ATT_STAGE_W;
        const uint32_t* KloW = KhiW + 2048;
        const uint32_t* VhW  = KhiW + 4096;
        const uint32_t* VlW  = KhiW + 6144;

        // ---- S = Q @ K^T (3-term bf16), frag-unit loads ----
        float sreg[8][4];
        #pragma unroll
        for (int nt = 0; nt < 8; nt++)
            #pragma unroll
            for (int c = 0; c < 4; c++) sreg[nt][c] = 0.0f;

        #pragma unroll
        for (int nt = 0; nt < 8; nt++) {
            const int j  = nt * 8 + grp;
            const int x7 = j & 7;
            const uint32_t* kh = KhiW + j * 32;
            const uint32_t* kl = KloW + j * 32;
            uint4 h0 = *(const uint4*)&kh[(u0 ^ x7) << 2];
            uint4 h1 = *(const uint4*)&kh[(u1 ^ x7) << 2];
            uint4 g0 = *(const uint4*)&kl[(u0 ^ x7) << 2];
            uint4 g1 = *(const uint4*)&kl[(u1 ^ x7) << 2];
            mma_bf16(sreg[nt], qh[0], h0.x, h0.y);
            mma_bf16(sreg[nt], qh[0], g0.x, g0.y);
            mma_bf16(sreg[nt], ql[0], h0.x, h0.y);
            mma_bf16(sreg[nt], qh[1], h0.z, h0.w);
            mma_bf16(sreg[nt], qh[1], g0.z, g0.w);
            mma_bf16(sreg[nt], ql[1], h0.z, h0.w);
            mma_bf16(sreg[nt], qh[2], h1.x, h1.y);
            mma_bf16(sreg[nt], qh[2], g1.x, g1.y);
            mma_bf16(sreg[nt], ql[2], h1.x, h1.y);
            mma_bf16(sreg[nt], qh[3], h1.z, h1.w);
            mma_bf16(sreg[nt], qh[3], g1.z, g1.w);
            mma_bf16(sreg[nt], ql[3], h1.z, h1.w);
        }

        // ---- scale + causal mask ----
        const float scale = 0.125f;
        if (kt == qt) {
            #pragma unroll
            for (int nt = 0; nt < 8; nt++)
                #pragma unroll
                for (int c = 0; c < 4; c++) {
                    int j = k0 + nt * 8 + 2 * qid + (c & 1);
                    int i = (c < 2) ? i0 : (i0 + 8);
                    float sv = sreg[nt][c] * scale;
                    if (j > i) sv = -1e30f;
                    sreg[nt][c] = sv;
                }
        } else {
            #pragma unroll
            for (int nt = 0; nt < 8; nt++)
                #pragma unroll
                for (int c = 0; c < 4; c++) sreg[nt][c] *= scale;
        }

        // ---- online softmax ----
        float mx0 = -1e30f, mx1 = -1e30f;
        #pragma unroll
        for (int nt = 0; nt < 8; nt++) {
            mx0 = fmaxf(mx0, fmaxf(sreg[nt][0], sreg[nt][1]));
            mx1 = fmaxf(mx1, fmaxf(sreg[nt][2], sreg[nt][3]));
        }
        #pragma unroll
        for (int off = 1; off <= 2; off <<= 1) {
            mx0 = fmaxf(mx0, __shfl_xor_sync(0xffffffffu, mx0, off));
            mx1 = fmaxf(mx1, __shfl_xor_sync(0xffffffffu, mx1, off));
        }
        float mn0 = fmaxf(m0f, mx0);
        float mn1 = fmaxf(m1f, mx1);
        float a0 = __expf(m0f - mn0);
        float a1 = __expf(m1f - mn1);
        m0f = mn0; m1f = mn1;
        #pragma unroll
        for (int nt = 0; nt < 8; nt++) {
            o[nt][0] *= a0;  o[nt][1] *= a0;
            o[nt][2] *= a1;  o[nt][3] *= a1;
        }

        // ---- exp + repack ALL P fragments first ----
        float rs0 = 0.0f, rs1 = 0.0f;
        uint32_t ph[4][4], pl[4][4];
        #pragma unroll
        for (int kc2 = 0; kc2 < 4; kc2++) {
            #pragma unroll
            for (int part = 0; part < 2; part++) {
                const int nt = kc2 * 2 + part;
                float p0 = __expf(sreg[nt][0] - mn0);
                float p1 = __expf(sreg[nt][1] - mn0);
                float p2 = __expf(sreg[nt][2] - mn1);
                float p3 = __expf(sreg[nt][3] - mn1);
                rs0 += p0 + p1;
                rs1 += p2 + p3;
                uint32_t u01 = pk_bf16(p0, p1);
                uint32_t u23 = pk_bf16(p2, p3);
                ph[kc2][2 * part]     = u01;
                ph[kc2][2 * part + 1] = u23;
                pl[kc2][2 * part]     = pk_bf16(p0 - bflo(u01), p1 - bfhi(u01));
                pl[kc2][2 * part + 1] = pk_bf16(p2 - bflo(u23), p3 - bfhi(u23));
            }
        }

        // ---- PV mma (3-term), one pass over V rows ----
        #pragma unroll
        for (int ont = 0; ont < 8; ont++) {
            const int d  = ont * 8 + grp;
            const int x7 = d & 7;
            const uint32_t* vh = VhW + d * 32;
            const uint32_t* vl = VlW + d * 32;
            uint4 h0 = *(const uint4*)&vh[(u0 ^ x7) << 2];
            uint4 h1 = *(const uint4*)&vh[(u1 ^ x7) << 2];
            uint4 g0 = *(const uint4*)&vl[(u0 ^ x7) << 2];
            uint4 g1 = *(const uint4*)&vl[(u1 ^ x7) << 2];
            mma_bf16(o[ont], ph[0], h0.x, h0.y);
            mma_bf16(o[ont], ph[0], g0.x, g0.y);
            mma_bf16(o[ont], pl[0], h0.x, h0.y);
            mma_bf16(o[ont], ph[1], h0.z, h0.w);
            mma_bf16(o[ont], ph[1], g0.z, g0.w);
            mma_bf16(o[ont], pl[1], h0.z, h0.w);
            mma_bf16(o[ont], ph[2], h1.x, h1.y);
            mma_bf16(o[ont], ph[2], g1.x, g1.y);
            mma_bf16(o[ont], pl[2], h1.x, h1.y);
            mma_bf16(o[ont], ph[3], h1.z, h1.w);
            mma_bf16(o[ont], ph[3], g1.z, g1.w);
            mma_bf16(o[ont], pl[3], h1.z, h1.w);
        }
        #pragma unroll
        for (int off = 1; off <= 2; off <<= 1) {
            rs0 += __shfl_xor_sync(0xffffffffu, rs0, off);
            rs1 += __shfl_xor_sync(0xffffffffu, rs1, off);
        }
        l0 = l0 * a0 + rs0;
        l1 = l1 * a1 + rs1;
    }

    // ---- epilogue: tf32-rounded store in FRAG-A layout (proj GEMM input) ----
    const float inv0 = 1.0f / l0;
    const float inv1 = 1.0f / l1;
    #pragma unroll
    for (int ont = 0; ont < 8; ont++) {
        #pragma unroll
        for (int c = 0; c < 4; c++) {
            int col = h * HDIM + ont * 8 + 2 * qid + (c & 1);
            int m   = b * LSEQ + i0 + ((c >> 1) << 3);
            float val = (c < 2) ? o[ont][c] * inv0 : o[ont][c] * inv1;
            int blk = (m >> 4) * (DMOD >> 3) + (col >> 3);
            int inner = ((m & 7) * 4 + (col & 3)) * 4
                      + ((col >> 2) & 1) * 2 + ((m >> 3) & 1);
            y[(size_t)blk * 128 + inner] = __uint_as_float(f2tf32(val));
        }
    }
}

// ===========================================================================
// Launch
// ===========================================================================
extern "C" void kernel_launch(void* const* d_in, const int* in_sizes, int n_in,
                              void* d_out, int out_size)
{
    (void)in_sizes; (void)n_in; (void)out_size;
    const float* x     = (const float*)d_in[0];
    const float* Wqkv  = (const float*)d_in[1];
    const float* bqkv  = (const float*)d_in[2];
    const float* Wproj = (const float*)d_in[3];
    const float* bproj = (const float*)d_in[4];
    float* out = (float*)d_out;

    float *qkvp, *yp, *xr, *wqkvr, *wprojr;
    uint32_t *kwp, *vwp;
    cudaGetSymbolAddress((void**)&qkvp, g_qkv);
    cudaGetSymbolAddress((void**)&yp, g_y);
    cudaGetSymbolAddress((void**)&xr, g_xr);
    cudaGetSymbolAddress((void**)&wqkvr, g_wqkvr);
    cudaGetSymbolAddress((void**)&wprojr, g_wprojr);
    cudaGetSymbolAddress((void**)&kwp, g_kw);
    cudaGetSymbolAddress((void**)&vwp, g_vw);

    static bool attr_set = false;
    if (!attr_set) {
        cudaFuncSetAttribute(gemm_tc, cudaFuncAttributeMaxDynamicSharedMemorySize,
                             GEMM_SMEM);
        cudaFuncSetAttribute(attn_mma, cudaFuncAttributeMaxDynamicSharedMemorySize,
                             ATTN_SMEM);
        attr_set = true;
    }

    // Pre-passes: round + relayout (warp-per-block, coalesced stores)
    {
        int nxb = (MROWS / 16) * (DMOD / 8);       // 65536 A blocks
        int nqb = (NQKV / 8) * (DMOD / 8);         // 49152 B blocks
        int npb = (DMOD / 8) * (DMOD / 8);         // 16384 B blocks
        xfrag_kernel<<<nxb / 8, 256>>>(x, xr, MROWS, DMOD);
        wfrag_kernel<<<nqb / 8, 256>>>(Wqkv, wqkvr, DMOD, NQKV);
        wfrag_kernel<<<npb / 8, 256>>>(Wproj, wprojr, DMOD, DMOD);
    }

    // QKV projection
    gemm_tc<<<dim3(NQKV / 128, MROWS / 128), 256, GEMM_SMEM>>>(
        xr, wqkvr, bqkv, qkvp, MROWS, NQKV, DMOD);
    // K/V -> frag-unit bf16 hi/lo tiles (smem-staged, coalesced stores)
    kvconv_kernel<<<dim3(32, 64), 128>>>(qkvp, kwp, vwp);
    // Causal flash attention (q-tile 64, 128 threads, 3 CTAs/SM)
    attn_mma<<<dim3(LSEQ / 64, BSZ * NHEAD), 128, ATTN_SMEM>>>(qkvp, kwp, vwp, yp);
    // Output projection
    gemm_tc<<<dim3(DMOD / 128, MROWS / 128), 256, GEMM_SMEM>>>(
        yp, wprojr, bproj, out, MROWS, DMOD, DMOD);
}